// round 6
// baseline (speedup 1.0000x reference)
#include <cuda_runtime.h>
#include <cstdint>

// Conv2d 3x3 s1 p1 via mma.sync tf32 implicit GEMM (compute_103-safe).
// Prepass: x -> tf32, zero-padded [img*ch][58][58]  => every tap read is dense,
// no per-tile masking. Main: CTA tile 128oc x 256px, K=1152 in 72 tiles of 16,
// 8 warps (warp tile 64x64), 3-stage cp.async pipeline for A and B.

#define HW    3136
#define PHW   3364           // 58*58
#define CIN   128
#define COUT  256
#define KTOT  1152
#define NKT   72
#define LDA   136
#define LDB   264
#define ATILEF (16*LDA)      // 2176 floats
#define BTILEF (16*LDB)      // 4224 floats
#define STAGEF (ATILEF+BTILEF)
#define NSTAGE 3
#define SMEM_BYTES (NSTAGE*STAGEF*4)   // 76800

__device__ float g_wt[KTOT * COUT];            // [k][oc] tf32, k = rs*128 + c
__device__ float g_xp[32 * CIN * PHW];         // padded tf32 x

__global__ void wt_kernel(const float* __restrict__ W) {
    const int k = blockIdx.x, oc = threadIdx.x;
    const int rs = k >> 7, c = k & 127;
    float v = W[oc * KTOT + c * 9 + rs];
    uint32_t t; asm("cvt.rna.tf32.f32 %0, %1;" : "=r"(t) : "f"(v));
    g_wt[k * COUT + oc] = __uint_as_float(t);
}

__global__ void xp_kernel(const float* __restrict__ x) {
    const int idx = blockIdx.x * 256 + threadIdx.x;
    if (idx >= 32 * CIN * PHW) return;
    const int cell = idx % PHW, ic = idx / PHW;
    const int ph = cell / 58, pw = cell - ph * 58;
    float v = 0.0f;
    if (ph >= 1 && ph <= 56 && pw >= 1 && pw <= 56)
        v = x[(size_t)ic * HW + (ph - 1) * 56 + (pw - 1)];
    uint32_t t; asm("cvt.rna.tf32.f32 %0, %1;" : "=r"(t) : "f"(v));
    g_xp[idx] = __uint_as_float(t);
}

__device__ __forceinline__ void cp16(uint32_t d, const void* s) {
    asm volatile("cp.async.cg.shared.global [%0], [%1], 16;" :: "r"(d), "l"(s));
}
__device__ __forceinline__ void cp4(uint32_t d, const void* s) {
    asm volatile("cp.async.ca.shared.global [%0], [%1], 4;" :: "r"(d), "l"(s));
}
#define CP_COMMIT asm volatile("cp.async.commit_group;" ::: "memory")
#define CP_WAIT1  asm volatile("cp.async.wait_group 1;" ::: "memory")

__global__ void __launch_bounds__(256, 1)
conv_mma(const float* __restrict__ bias, float* __restrict__ out)
{
    extern __shared__ float sm[];
    const uint32_t smb = (uint32_t)__cvta_generic_to_shared(sm);
    const int tid  = threadIdx.x;
    const int lane = tid & 31;
    const int wid  = tid >> 5;            // 0..7
    const int r    = lane >> 2, cq = lane & 3;
    const int p0   = blockIdx.x * 256;    // pixel tile (256 px)
    const int ni   = blockIdx.y;
    const int m0   = blockIdx.z * 128;    // oc tile
    const int wm0  = (wid & 1) * 64;
    const int wn0  = (wid >> 1) * 64;

    // B loader mapping: 16 channel-rows x 16 col-threads, each thread 16 px
    const int brow = tid >> 4;
    const int bct  = tid & 15;
    int boff[16];                          // padded-layout offset of each px
#pragma unroll
    for (int j = 0; j < 16; j++) {
        int px = p0 + bct + 16 * j;
        if (px >= HW) px = HW - 1;         // clamp; epilogue discards
        const int oh = px / 56, ow = px - oh * 56;
        boff[j] = oh * 58 + ow;            // +rr*58+sc added per tap
    }
    const float* xpb = g_xp + (size_t)(ni * CIN + brow) * PHW;

    float acc[4][8][4];
#pragma unroll
    for (int mf = 0; mf < 4; mf++)
#pragma unroll
        for (int nf = 0; nf < 8; nf++)
#pragma unroll
            for (int e = 0; e < 4; e++) acc[mf][nf][e] = 0.0f;

    auto issue = [&](int kt) {
        const int st = kt % NSTAGE;
        const uint32_t As = smb + st * (STAGEF * 4);
        const uint32_t Bs = As + ATILEF * 4;
        // A: 16 x 128, two cp16 per thread
#pragma unroll
        for (int q = 0; q < 2; q++) {
            const int idx = tid + q * 256;
            const int row = idx >> 5, col = (idx & 31) * 4;
            cp16(As + (row * LDA + col) * 4,
                 g_wt + (size_t)(kt * 16 + row) * COUT + m0 + col);
        }
        // B: 16 ch x 256 px from padded input (always valid)
        const int rs = kt >> 3, c0 = (kt & 7) * 16;
        const int rr = rs / 3, sc = rs - rr * 3;
        const float* src = xpb + (size_t)c0 * PHW + rr * 58 + sc;
        const uint32_t dst = Bs + (brow * LDB + bct) * 4;
#pragma unroll
        for (int j = 0; j < 16; j++)
            cp4(dst + j * 64, src + boff[j]);
    };

    issue(0); CP_COMMIT;
    issue(1); CP_COMMIT;

#pragma unroll 1
    for (int kt = 0; kt < NKT; kt++) {
        const int st = kt % NSTAGE;
        CP_WAIT1;
        __syncthreads();

        if (kt + 2 < NKT) issue(kt + 2);
        CP_COMMIT;

        const float* Asf = sm + st * STAGEF;
        const float* Bsf = Asf + ATILEF;
#pragma unroll
        for (int ks = 0; ks < 2; ks++) {
            uint32_t a[4][4], b[8][2];
            const float* ap = Asf + (ks * 8 + cq) * LDA + wm0 + r;
#pragma unroll
            for (int mf = 0; mf < 4; mf++) {
                a[mf][0] = __float_as_uint(ap[mf * 16]);
                a[mf][1] = __float_as_uint(ap[mf * 16 + 8]);
                a[mf][2] = __float_as_uint(ap[4 * LDA + mf * 16]);
                a[mf][3] = __float_as_uint(ap[4 * LDA + mf * 16 + 8]);
            }
            const float* bp = Bsf + (ks * 8 + cq) * LDB + wn0 + r;
#pragma unroll
            for (int nf = 0; nf < 8; nf++) {
                b[nf][0] = __float_as_uint(bp[nf * 8]);
                b[nf][1] = __float_as_uint(bp[4 * LDB + nf * 8]);
            }
#pragma unroll
            for (int mf = 0; mf < 4; mf++)
#pragma unroll
                for (int nf = 0; nf < 8; nf++)
                    asm volatile(
                        "mma.sync.aligned.m16n8k8.row.col.f32.tf32.tf32.f32 "
                        "{%0,%1,%2,%3}, {%4,%5,%6,%7}, {%8,%9}, {%0,%1,%2,%3};"
                        : "+f"(acc[mf][nf][0]), "+f"(acc[mf][nf][1]),
                          "+f"(acc[mf][nf][2]), "+f"(acc[mf][nf][3])
                        : "r"(a[mf][0]), "r"(a[mf][1]), "r"(a[mf][2]), "r"(a[mf][3]),
                          "r"(b[nf][0]), "r"(b[nf][1]));
        }
    }

    // ---- epilogue ----
    const size_t obase = (size_t)ni * COUT * HW;
#pragma unroll
    for (int mf = 0; mf < 4; mf++) {
        const int mg = m0 + wm0 + mf * 16 + r;
        const float b0 = __ldg(bias + mg);
        const float b1 = __ldg(bias + mg + 8);
        float* o0 = out + obase + (size_t)mg * HW;
#pragma unroll
        for (int nf = 0; nf < 8; nf++) {
            const int px = p0 + wn0 + nf * 8 + cq * 2;
            if (px < HW) {
                float2 v0 = make_float2(acc[mf][nf][0] + b0, acc[mf][nf][1] + b0);
                float2 v1 = make_float2(acc[mf][nf][2] + b1, acc[mf][nf][3] + b1);
                *reinterpret_cast<float2*>(o0 + px) = v0;
                *reinterpret_cast<float2*>(o0 + (size_t)8 * HW + px) = v1;
            }
        }
    }
}

extern "C" void kernel_launch(void* const* d_in, const int* in_sizes, int n_in,
                              void* d_out, int out_size)
{
    const float* x    = (const float*)d_in[0];
    const float* W    = (const float*)d_in[1];
    const float* bias = (const float*)d_in[2];
    float* out        = (float*)d_out;

    cudaFuncSetAttribute(conv_mma, cudaFuncAttributeMaxDynamicSharedMemorySize,
                         SMEM_BYTES);

    wt_kernel<<<KTOT, COUT>>>(W);
    xp_kernel<<<(32 * CIN * PHW + 255) / 256, 256>>>(x);

    dim3 grid(13, 32, 2);   // ceil(3136/256)=13 px-tiles x 32 img x 2 oc-tiles
    conv_mma<<<grid, 256, SMEM_BYTES>>>(bias, out);
}

// round 7
// speedup vs baseline: 1.8160x; 1.8160x over previous
#include <cuda_runtime.h>
#include <cuda_fp16.h>
#include <cstdint>

// Conv2d 3x3 s1 p1 via mma.sync m16n8k16 FP16 (f32 accum) implicit GEMM.
// k tap-major: kt (0..71) = 16 k-values = one tap (kt>>3), channels (kt&7)*16+..
// A (weights): prepass packs per-thread fragment records -> direct LDG.128,
//              register double-buffered, no smem.
// B (pixels):  prepass packs fp16 channel-pairs into zero-padded [cpair][58x58];
//              per kt a dense 8x140-word span via cp.async (3-stage smem).

#define HW    3136
#define PHW   3364            // 58*58 (words per channel-pair image)
#define CIN   128
#define COUT  256
#define KTOT  1152
#define NKT   72
#define LDBW  140             // words per B smem row
#define BROWS 8               // channel-pairs per k16 tile
#define BSTGW (BROWS*LDBW)    // 1120 words per stage
#define NSTAGE 3

__device__ __align__(16) uint32_t g_wf[NKT * 2 * 2 * 32 * 16];        // 1.18MB frags
__device__ __align__(16) uint32_t g_xh[32 * 64 * PHW + 1024];         // 27.6MB packed x

// ---- prepass: weight fragments ----
// word w: reg=w&3, mf=(w>>2)&3, lane=(w>>4)&31, wmg=(w>>9)&1, oct=(w>>10)&1, kt=w>>11
__global__ void wf_kernel(const float* __restrict__ W) {
    const int w = blockIdx.x * 256 + threadIdx.x;
    const int reg = w & 3, mf = (w >> 2) & 3, lane = (w >> 4) & 31;
    const int wmg = (w >> 9) & 1, oct = (w >> 10) & 1, kt = w >> 11;
    const int r = lane >> 2, cq = lane & 3;
    const int oc = oct * 128 + wmg * 64 + mf * 16 + r + (reg & 1) * 8;
    const int klocal = 2 * cq + ((reg & 2) ? 8 : 0);
    const int c = (kt & 7) * 16 + klocal;
    const int rs = kt >> 3;
    const float lo = W[oc * KTOT + c * 9 + rs];
    const float hi = W[oc * KTOT + (c + 1) * 9 + rs];
    const __half2 h = __floats2half2_rn(lo, hi);
    g_wf[w] = *reinterpret_cast<const uint32_t*>(&h);
}

// ---- prepass: x -> fp16 channel-pair packed, zero-padded ----
__global__ void xh_kernel(const float* __restrict__ x) {
    const int idx = blockIdx.x * 256 + threadIdx.x;   // grid sized exactly
    const int cell = idx % PHW;
    const int cp = (idx / PHW) & 63;
    const int ni = idx / (PHW * 64);
    const int ph = cell / 58, pw = cell - ph * 58;
    float lo = 0.0f, hi = 0.0f;
    if (ph >= 1 && ph <= 56 && pw >= 1 && pw <= 56) {
        const size_t base = ((size_t)ni * CIN + 2 * cp) * HW + (ph - 1) * 56 + (pw - 1);
        lo = x[base];
        hi = x[base + HW];
    }
    const __half2 h = __floats2half2_rn(lo, hi);
    g_xh[idx] = *reinterpret_cast<const uint32_t*>(&h);
}

__device__ __forceinline__ void cp16(uint32_t d, const void* s) {
    asm volatile("cp.async.cg.shared.global [%0], [%1], 16;" :: "r"(d), "l"(s));
}
#define CP_COMMIT asm volatile("cp.async.commit_group;" ::: "memory")
#define CP_WAIT1  asm volatile("cp.async.wait_group 1;" ::: "memory")

__global__ void __launch_bounds__(128, 2)
conv_mma(const float* __restrict__ bias, float* __restrict__ out)
{
    __shared__ uint32_t smB[NSTAGE * BSTGW];
    const uint32_t smb = (uint32_t)__cvta_generic_to_shared(smB);
    const int tid  = threadIdx.x;
    const int lane = tid & 31;
    const int wid  = tid >> 5;
    const int r    = lane >> 2, cq = lane & 3;
    const int p0   = blockIdx.x * 128;
    const int ni   = blockIdx.y;
    const int oct  = blockIdx.z;
    const int wmg  = wid & 1;
    const int wn0  = (wid >> 1) * 64;

    const int oh0 = p0 / 56, ow0 = p0 - oh0 * 56;
    const int base0 = oh0 * 58 + ow0;

    // per-thread B-fragment pixel offsets (relative to base0)
    int pxrel[8];
#pragma unroll
    for (int nf = 0; nf < 8; nf++) {
        const int px = p0 + wn0 + nf * 8 + r;
        const int oh = px / 56, ow = px - oh * 56;
        pxrel[nf] = oh * 58 + ow - base0;
    }

    // B loader: 280 items = 8 rows x 35 cp16; thread handles items tid, tid+128, tid+256
    int itrow[3], itcol[3];
#pragma unroll
    for (int q = 0; q < 3; q++) {
        const int it = tid + q * 128;
        itrow[q] = it / 35;
        itcol[q] = it - itrow[q] * 35;
    }
    const uint32_t* xim = g_xh + (size_t)ni * (64 * PHW);

    float acc[4][8][4];
#pragma unroll
    for (int mf = 0; mf < 4; mf++)
#pragma unroll
        for (int nf = 0; nf < 8; nf++)
#pragma unroll
            for (int e = 0; e < 4; e++) acc[mf][nf][e] = 0.0f;

    auto issueB = [&](int kt) {
        const int tap = kt >> 3;
        const int rr = tap / 3, sc = tap - rr * 3;
        const int cp0 = (kt & 7) * 8;
        const int abase = (base0 + rr * 58 + sc) & ~3;
        const uint32_t dst = smb + (kt % NSTAGE) * (BSTGW * 4);
#pragma unroll
        for (int q = 0; q < 3; q++) {
            if (q == 2 && tid >= 24) break;
            cp16(dst + (itrow[q] * LDBW + itcol[q] * 4) * 4,
                 xim + (size_t)(cp0 + itrow[q]) * PHW + abase + itcol[q] * 4);
        }
    };

    const uint32_t* wf0 = g_wf + ((size_t)oct * 2 + wmg) * 512 + lane * 16;
    auto loadA = [&](int kt, uint32_t a[16]) {
        const uint4* p = reinterpret_cast<const uint4*>(wf0 + (size_t)kt * 2048);
#pragma unroll
        for (int q = 0; q < 4; q++) {
            const uint4 v = p[q];
            a[q * 4 + 0] = v.x; a[q * 4 + 1] = v.y;
            a[q * 4 + 2] = v.z; a[q * 4 + 3] = v.w;
        }
    };

    issueB(0); CP_COMMIT;
    issueB(1); CP_COMMIT;

    uint32_t acur[16], anxt[16];
    loadA(0, acur);

#pragma unroll 1
    for (int kt = 0; kt < NKT; kt++) {
        CP_WAIT1;
        __syncthreads();

        if (kt + 2 < NKT) issueB(kt + 2);
        CP_COMMIT;
        if (kt + 1 < NKT) loadA(kt + 1, anxt);

        const int tap = kt >> 3;
        const int rr = tap / 3, sc = tap - rr * 3;
        const int amod = (base0 + rr * 58 + sc) & 3;
        const uint32_t* Bsf = smB + (kt % NSTAGE) * BSTGW + amod;

        uint32_t b[8][2];
#pragma unroll
        for (int nf = 0; nf < 8; nf++) {
            b[nf][0] = Bsf[cq * LDBW + pxrel[nf]];
            b[nf][1] = Bsf[(cq + 4) * LDBW + pxrel[nf]];
        }
#pragma unroll
        for (int mf = 0; mf < 4; mf++)
#pragma unroll
            for (int nf = 0; nf < 8; nf++)
                asm volatile(
                    "mma.sync.aligned.m16n8k16.row.col.f32.f16.f16.f32 "
                    "{%0,%1,%2,%3}, {%4,%5,%6,%7}, {%8,%9}, {%0,%1,%2,%3};"
                    : "+f"(acc[mf][nf][0]), "+f"(acc[mf][nf][1]),
                      "+f"(acc[mf][nf][2]), "+f"(acc[mf][nf][3])
                    : "r"(acur[mf * 4 + 0]), "r"(acur[mf * 4 + 1]),
                      "r"(acur[mf * 4 + 2]), "r"(acur[mf * 4 + 3]),
                      "r"(b[nf][0]), "r"(b[nf][1]));

#pragma unroll
        for (int q = 0; q < 16; q++) acur[q] = anxt[q];
    }

    // ---- epilogue (same D layout as R4) ----
    const size_t obase = (size_t)ni * COUT * HW;
#pragma unroll
    for (int mf = 0; mf < 4; mf++) {
        const int mg = oct * 128 + wmg * 64 + mf * 16 + r;
        const float b0 = __ldg(bias + mg);
        const float b1 = __ldg(bias + mg + 8);
        float* o0 = out + obase + (size_t)mg * HW;
#pragma unroll
        for (int nf = 0; nf < 8; nf++) {
            const int px = p0 + wn0 + nf * 8 + cq * 2;
            if (px < HW) {
                float2 v0 = make_float2(acc[mf][nf][0] + b0, acc[mf][nf][1] + b0);
                float2 v1 = make_float2(acc[mf][nf][2] + b1, acc[mf][nf][3] + b1);
                *reinterpret_cast<float2*>(o0 + px) = v0;
                *reinterpret_cast<float2*>(o0 + (size_t)8 * HW + px) = v1;
            }
        }
    }
}

extern "C" void kernel_launch(void* const* d_in, const int* in_sizes, int n_in,
                              void* d_out, int out_size)
{
    const float* x    = (const float*)d_in[0];
    const float* W    = (const float*)d_in[1];
    const float* bias = (const float*)d_in[2];
    float* out        = (float*)d_out;

    wf_kernel<<<NKT * 2 * 2 * 32 * 16 / 256, 256>>>(W);     // 1152 blocks
    xh_kernel<<<32 * 64 * PHW / 256, 256>>>(x);             // 26912 blocks

    dim3 grid(25, 32, 2);
    conv_mma<<<grid, 128>>>(bias, out);
}

// round 8
// speedup vs baseline: 2.2300x; 1.2280x over previous
#include <cuda_runtime.h>
#include <cuda_fp16.h>
#include <cstdint>

// Conv2d 3x3 s1 p1 via mma.sync m16n8k16 FP16 (f32 accum) implicit GEMM.
// K tap-major; K=32 per mainloop iteration (36 iters), processed as two k16
// halves. A (weights): prepass packs per-thread fragment records -> LDG.128,
// software-pipelined, no smem. B (pixels): prepass packs fp16 channel-pairs
// into zero-padded [cpair][58x58]; 16 rows x 140 words per iter via cp.async.

#define HW    3136
#define PHW   3364            // 58*58
#define CIN   128
#define COUT  256
#define KTOT  1152
#define NK32  36
#define LDBW  140
#define BROWS 16              // channel-pairs per k32 tile
#define BSTGW (BROWS*LDBW)    // 2240 words per stage
#define NSTAGE 3

__device__ __align__(16) uint32_t g_wf[72 * 2 * 2 * 32 * 16];     // kt16-indexed frags
__device__ __align__(16) uint32_t g_xh[32 * 64 * PHW + 1024];     // packed fp16 x

// word w: reg=w&3, mf=(w>>2)&3, lane=(w>>4)&31, wmg=(w>>9)&1, oct=(w>>10)&1, kt16=w>>11
__global__ void wf_kernel(const float* __restrict__ W) {
    const int w = blockIdx.x * 256 + threadIdx.x;
    const int reg = w & 3, mf = (w >> 2) & 3, lane = (w >> 4) & 31;
    const int wmg = (w >> 9) & 1, oct = (w >> 10) & 1, kt = w >> 11;
    const int r = lane >> 2, cq = lane & 3;
    const int oc = oct * 128 + wmg * 64 + mf * 16 + r + (reg & 1) * 8;
    const int klocal = 2 * cq + ((reg & 2) ? 8 : 0);
    const int c = (kt & 7) * 16 + klocal;
    const int rs = kt >> 3;
    const __half2 h = __floats2half2_rn(W[oc * KTOT + c * 9 + rs],
                                        W[oc * KTOT + (c + 1) * 9 + rs]);
    g_wf[w] = *reinterpret_cast<const uint32_t*>(&h);
}

__global__ void xh_kernel(const float* __restrict__ x) {
    const int idx = blockIdx.x * 256 + threadIdx.x;
    const int cell = idx % PHW;
    const int cp = (idx / PHW) & 63;
    const int ni = idx / (PHW * 64);
    const int ph = cell / 58, pw = cell - ph * 58;
    float lo = 0.0f, hi = 0.0f;
    if (ph >= 1 && ph <= 56 && pw >= 1 && pw <= 56) {
        const size_t base = ((size_t)ni * CIN + 2 * cp) * HW + (ph - 1) * 56 + (pw - 1);
        lo = x[base];
        hi = x[base + HW];
    }
    const __half2 h = __floats2half2_rn(lo, hi);
    g_xh[idx] = *reinterpret_cast<const uint32_t*>(&h);
}

__device__ __forceinline__ void cp16(uint32_t d, const void* s) {
    asm volatile("cp.async.cg.shared.global [%0], [%1], 16;" :: "r"(d), "l"(s));
}
#define CP_COMMIT asm volatile("cp.async.commit_group;" ::: "memory")
#define CP_WAIT1  asm volatile("cp.async.wait_group 1;" ::: "memory")

#define MMA16(acc, a, b0, b1) \
    asm volatile("mma.sync.aligned.m16n8k16.row.col.f32.f16.f16.f32 " \
        "{%0,%1,%2,%3}, {%4,%5,%6,%7}, {%8,%9}, {%0,%1,%2,%3};" \
        : "+f"((acc)[0]), "+f"((acc)[1]), "+f"((acc)[2]), "+f"((acc)[3]) \
        : "r"((a)[0]), "r"((a)[1]), "r"((a)[2]), "r"((a)[3]), "r"(b0), "r"(b1))

__global__ void __launch_bounds__(128, 2)
conv_mma(const float* __restrict__ bias, float* __restrict__ out)
{
    __shared__ uint32_t smB[NSTAGE * BSTGW];
    const uint32_t smb = (uint32_t)__cvta_generic_to_shared(smB);
    const int tid  = threadIdx.x;
    const int lane = tid & 31;
    const int wid  = tid >> 5;
    const int r    = lane >> 2, cq = lane & 3;
    const int p0   = blockIdx.x * 128;
    const int ni   = blockIdx.y;
    const int oct  = blockIdx.z;
    const int wmg  = wid & 1;
    const int wn0  = (wid >> 1) * 64;

    const int oh0 = p0 / 56, ow0 = p0 - oh0 * 56;
    const int base0 = oh0 * 58 + ow0;

    int pxrel[8];
#pragma unroll
    for (int nf = 0; nf < 8; nf++) {
        const int px = p0 + wn0 + nf * 8 + r;
        const int oh = px / 56, ow = px - oh * 56;
        pxrel[nf] = oh * 58 + ow - base0;
    }

    // B loader: 560 items = 16 rows x 35 cp16; thread handles tid + q*128, q<5
    int itrow[5], itcol[5];
#pragma unroll
    for (int q = 0; q < 5; q++) {
        const int it = tid + q * 128;
        itrow[q] = it / 35;
        itcol[q] = it - itrow[q] * 35;
    }
    const uint32_t* xim = g_xh + (size_t)ni * (64 * PHW);

    float acc[4][8][4];
#pragma unroll
    for (int mf = 0; mf < 4; mf++)
#pragma unroll
        for (int nf = 0; nf < 8; nf++)
#pragma unroll
            for (int e = 0; e < 4; e++) acc[mf][nf][e] = 0.0f;

    auto issueB = [&](int kt) {               // kt in [0,36)
        const int tap = kt >> 2;
        const int rr = tap / 3, sc = tap - rr * 3;
        const int cp0 = (kt & 3) * 16;
        const int abase = (base0 + rr * 58 + sc) & ~3;
        const uint32_t dst = smb + (kt % NSTAGE) * (BSTGW * 4);
#pragma unroll
        for (int q = 0; q < 5; q++) {
            if (q == 4 && tid >= 48) break;
            cp16(dst + (itrow[q] * LDBW + itcol[q] * 4) * 4,
                 xim + (size_t)(cp0 + itrow[q]) * PHW + abase + itcol[q] * 4);
        }
    };

    const uint32_t* wf0 = g_wf + ((size_t)oct * 2 + wmg) * 512 + lane * 16;
    auto loadA = [&](int kt16, uint32_t a[16]) {
        const uint4* p = reinterpret_cast<const uint4*>(wf0 + (size_t)kt16 * 2048);
#pragma unroll
        for (int q = 0; q < 4; q++) {
            const uint4 v = p[q];
            a[q * 4 + 0] = v.x; a[q * 4 + 1] = v.y;
            a[q * 4 + 2] = v.z; a[q * 4 + 3] = v.w;
        }
    };

    issueB(0); CP_COMMIT;
    issueB(1); CP_COMMIT;

    uint32_t a0[16], a1[16];
    loadA(0, a0);

#pragma unroll 1
    for (int kt = 0; kt < NK32; kt++) {
        CP_WAIT1;
        __syncthreads();

        if (kt + 2 < NK32) issueB(kt + 2);
        CP_COMMIT;
        loadA(2 * kt + 1, a1);                 // second half of this kt

        const int tap = kt >> 2;
        const int rr = tap / 3, sc = tap - rr * 3;
        const int amod = (base0 + rr * 58 + sc) & 3;
        const uint32_t* Bsf = smB + (kt % NSTAGE) * BSTGW + amod;

        // ---- half 0 (rows 0..7) ----
        {
            uint32_t b[8][2];
#pragma unroll
            for (int nf = 0; nf < 8; nf++) {
                b[nf][0] = Bsf[cq * LDBW + pxrel[nf]];
                b[nf][1] = Bsf[(cq + 4) * LDBW + pxrel[nf]];
            }
#pragma unroll
            for (int mf = 0; mf < 4; mf++)
#pragma unroll
                for (int nf = 0; nf < 8; nf++)
                    MMA16(acc[mf][nf], a0 + mf * 4, b[nf][0], b[nf][1]);
        }

        if (kt + 1 < NK32) loadA(2 * (kt + 1), a0);   // first half of next kt

        // ---- half 1 (rows 8..15) ----
        {
            uint32_t b[8][2];
#pragma unroll
            for (int nf = 0; nf < 8; nf++) {
                b[nf][0] = Bsf[(8 + cq) * LDBW + pxrel[nf]];
                b[nf][1] = Bsf[(12 + cq) * LDBW + pxrel[nf]];
            }
#pragma unroll
            for (int mf = 0; mf < 4; mf++)
#pragma unroll
                for (int nf = 0; nf < 8; nf++)
                    MMA16(acc[mf][nf], a1 + mf * 4, b[nf][0], b[nf][1]);
        }
    }

    // ---- epilogue ----
    const size_t obase = (size_t)ni * COUT * HW;
#pragma unroll
    for (int mf = 0; mf < 4; mf++) {
        const int mg = oct * 128 + wmg * 64 + mf * 16 + r;
        const float b0 = __ldg(bias + mg);
        const float b1 = __ldg(bias + mg + 8);
        float* o0 = out + obase + (size_t)mg * HW;
#pragma unroll
        for (int nf = 0; nf < 8; nf++) {
            const int px = p0 + wn0 + nf * 8 + cq * 2;
            if (px < HW) {
                float2 v0 = make_float2(acc[mf][nf][0] + b0, acc[mf][nf][1] + b0);
                float2 v1 = make_float2(acc[mf][nf][2] + b1, acc[mf][nf][3] + b1);
                *reinterpret_cast<float2*>(o0 + px) = v0;
                *reinterpret_cast<float2*>(o0 + (size_t)8 * HW + px) = v1;
            }
        }
    }
}

extern "C" void kernel_launch(void* const* d_in, const int* in_sizes, int n_in,
                              void* d_out, int out_size)
{
    const float* x    = (const float*)d_in[0];
    const float* W    = (const float*)d_in[1];
    const float* bias = (const float*)d_in[2];
    float* out        = (float*)d_out;

    wf_kernel<<<72 * 2 * 2 * 32 * 16 / 256, 256>>>(W);
    xh_kernel<<<32 * 64 * PHW / 256, 256>>>(x);

    dim3 grid(25, 32, 2);
    conv_mma<<<grid, 128>>>(bias, out);
}

// round 9
// speedup vs baseline: 2.4222x; 1.0862x over previous
#include <cuda_runtime.h>
#include <cuda_fp16.h>
#include <cstdint>

// Conv2d 3x3 s1 p1 via mma.sync m16n8k16 FP16 (f32 accum) implicit GEMM.
// K tap-major; K=64 per mainloop iteration (18 iters), 4 k16 halves each.
// A (weights): prepass packs per-thread fragment records; LDG.128 pair-wise
// double-buffered with prefetch distance 2 halves (~256 cyc > L2 latency).
// B (pixels): prepass packs fp16 channel-pairs into zero-padded [cpair][58x58];
// 32 rows x 140 words per iter via cp.async (3-stage dynamic smem).

#define HW    3136
#define PHW   3364            // 58*58
#define CIN   128
#define COUT  256
#define KTOT  1152
#define NK64  18
#define LDBW  140
#define BROWS 32              // channel-pairs per k64 tile
#define BSTGW (BROWS*LDBW)    // 4480 words per stage
#define NSTAGE 3
#define SMEM_BYTES (NSTAGE*BSTGW*4)   // 53760

__device__ __align__(16) uint32_t g_wf[72 * 2 * 2 * 32 * 16];     // kt16-indexed frags
__device__ __align__(16) uint32_t g_xh[32 * 64 * PHW + 1024];     // packed fp16 x

// word w: reg=w&3, mf=(w>>2)&3, lane=(w>>4)&31, wmg=(w>>9)&1, oct=(w>>10)&1, kt16=w>>11
__global__ void wf_kernel(const float* __restrict__ W) {
    const int w = blockIdx.x * 256 + threadIdx.x;
    const int reg = w & 3, mf = (w >> 2) & 3, lane = (w >> 4) & 31;
    const int wmg = (w >> 9) & 1, oct = (w >> 10) & 1, kt = w >> 11;
    const int r = lane >> 2, cq = lane & 3;
    const int oc = oct * 128 + wmg * 64 + mf * 16 + r + (reg & 1) * 8;
    const int klocal = 2 * cq + ((reg & 2) ? 8 : 0);
    const int c = (kt & 7) * 16 + klocal;
    const int rs = kt >> 3;
    const __half2 h = __floats2half2_rn(W[oc * KTOT + c * 9 + rs],
                                        W[oc * KTOT + (c + 1) * 9 + rs]);
    g_wf[w] = *reinterpret_cast<const uint32_t*>(&h);
}

__global__ void xh_kernel(const float* __restrict__ x) {
    const int idx = blockIdx.x * 256 + threadIdx.x;
    const int cell = idx % PHW;
    const int cp = (idx / PHW) & 63;
    const int ni = idx / (PHW * 64);
    const int ph = cell / 58, pw = cell - ph * 58;
    float lo = 0.0f, hi = 0.0f;
    if (ph >= 1 && ph <= 56 && pw >= 1 && pw <= 56) {
        const size_t base = ((size_t)ni * CIN + 2 * cp) * HW + (ph - 1) * 56 + (pw - 1);
        lo = x[base];
        hi = x[base + HW];
    }
    const __half2 h = __floats2half2_rn(lo, hi);
    g_xh[idx] = *reinterpret_cast<const uint32_t*>(&h);
}

__device__ __forceinline__ void cp16(uint32_t d, const void* s) {
    asm volatile("cp.async.cg.shared.global [%0], [%1], 16;" :: "r"(d), "l"(s));
}
#define CP_COMMIT asm volatile("cp.async.commit_group;" ::: "memory")
#define CP_WAIT1  asm volatile("cp.async.wait_group 1;" ::: "memory")

#define MMA16(acc, a, b0, b1) \
    asm volatile("mma.sync.aligned.m16n8k16.row.col.f32.f16.f16.f32 " \
        "{%0,%1,%2,%3}, {%4,%5,%6,%7}, {%8,%9}, {%0,%1,%2,%3};" \
        : "+f"((acc)[0]), "+f"((acc)[1]), "+f"((acc)[2]), "+f"((acc)[3]) \
        : "r"((a)[0]), "r"((a)[1]), "r"((a)[2]), "r"((a)[3]), "r"(b0), "r"(b1))

__global__ void __launch_bounds__(128, 2)
conv_mma(const float* __restrict__ bias, float* __restrict__ out)
{
    extern __shared__ uint32_t smB[];
    const uint32_t smb = (uint32_t)__cvta_generic_to_shared(smB);
    const int tid  = threadIdx.x;
    const int lane = tid & 31;
    const int wid  = tid >> 5;
    const int r    = lane >> 2, cq = lane & 3;
    const int p0   = blockIdx.x * 128;
    const int ni   = blockIdx.y;
    const int oct  = blockIdx.z;
    const int wmg  = wid & 1;
    const int wn0  = (wid >> 1) * 64;

    const int oh0 = p0 / 56, ow0 = p0 - oh0 * 56;
    const int base0 = oh0 * 58 + ow0;

    int pxrel[8];
#pragma unroll
    for (int nf = 0; nf < 8; nf++) {
        const int px = p0 + wn0 + nf * 8 + r;
        const int oh = px / 56, ow = px - oh * 56;
        pxrel[nf] = oh * 58 + ow - base0;
    }

    const uint32_t* xim = g_xh + (size_t)ni * (64 * PHW);

    float acc[4][8][4];
#pragma unroll
    for (int mf = 0; mf < 4; mf++)
#pragma unroll
        for (int nf = 0; nf < 8; nf++)
#pragma unroll
            for (int e = 0; e < 4; e++) acc[mf][nf][e] = 0.0f;

    // B loader: 1120 items = 32 rows x 35 cp16; thread covers tid + q*128, q<9
    auto issueB = [&](int kt) {               // kt in [0,18)
        const int tap = kt >> 1;
        const int rr = tap / 3, sc = tap - rr * 3;
        const int cp0 = (kt & 1) * 32;
        const int abase = (base0 + rr * 58 + sc) & ~3;
        const uint32_t dst = smb + (kt % NSTAGE) * (BSTGW * 4);
#pragma unroll
        for (int q = 0; q < 9; q++) {
            const int it = tid + q * 128;
            if (q == 8 && it >= 1120) break;
            const int row = it / 35;
            const int col = it - row * 35;
            cp16(dst + (row * LDBW + col * 4) * 4,
                 xim + (size_t)(cp0 + row) * PHW + abase + col * 4);
        }
    };

    const uint32_t* wf0 = g_wf + ((size_t)oct * 2 + wmg) * 512 + lane * 16;
    // load A fragments for k16 pair P (kt16 = 2P, 2P+1) -> 32 words
    auto loadA2 = [&](int P, uint32_t a[32]) {
        const uint4* p = reinterpret_cast<const uint4*>(wf0 + (size_t)(2 * P) * 2048);
        const uint4* p2 = reinterpret_cast<const uint4*>(wf0 + (size_t)(2 * P + 1) * 2048);
#pragma unroll
        for (int q = 0; q < 4; q++) {
            const uint4 v = p[q];
            a[q * 4 + 0] = v.x; a[q * 4 + 1] = v.y;
            a[q * 4 + 2] = v.z; a[q * 4 + 3] = v.w;
        }
#pragma unroll
        for (int q = 0; q < 4; q++) {
            const uint4 v = p2[q];
            a[16 + q * 4 + 0] = v.x; a[16 + q * 4 + 1] = v.y;
            a[16 + q * 4 + 2] = v.z; a[16 + q * 4 + 3] = v.w;
        }
    };

    issueB(0); CP_COMMIT;
    issueB(1); CP_COMMIT;

    uint32_t Ab[2][32];
    loadA2(0, Ab[0]);

#pragma unroll 1
    for (int kt = 0; kt < NK64; kt++) {
        CP_WAIT1;
        __syncthreads();

        if (kt + 2 < NK64) issueB(kt + 2);
        CP_COMMIT;

        const int tap = kt >> 1;
        const int rr = tap / 3, sc = tap - rr * 3;
        const int amod = (base0 + rr * 58 + sc) & 3;
        const uint32_t* Bsf = smB + (kt % NSTAGE) * BSTGW + amod;

#pragma unroll
        for (int s = 0; s < 2; s++) {          // k16-pair within this kt64
            const int P = 2 * kt + s;
            if (P + 1 < 36) loadA2(P + 1, Ab[s ^ 1]);
#pragma unroll
            for (int h2 = 0; h2 < 2; h2++) {   // k16 half within pair
                const int hrow = (2 * s + h2) * 8;
                uint32_t b[8][2];
#pragma unroll
                for (int nf = 0; nf < 8; nf++) {
                    b[nf][0] = Bsf[(hrow + cq) * LDBW + pxrel[nf]];
                    b[nf][1] = Bsf[(hrow + cq + 4) * LDBW + pxrel[nf]];
                }
                const uint32_t* af = Ab[s] + h2 * 16;
#pragma unroll
                for (int mf = 0; mf < 4; mf++)
#pragma unroll
                    for (int nf = 0; nf < 8; nf++)
                        MMA16(acc[mf][nf], af + mf * 4, b[nf][0], b[nf][1]);
            }
        }
    }

    // ---- epilogue ----
    const size_t obase = (size_t)ni * COUT * HW;
#pragma unroll
    for (int mf = 0; mf < 4; mf++) {
        const int mg = oct * 128 + wmg * 64 + mf * 16 + r;
        const float b0 = __ldg(bias + mg);
        const float b1 = __ldg(bias + mg + 8);
        float* o0 = out + obase + (size_t)mg * HW;
#pragma unroll
        for (int nf = 0; nf < 8; nf++) {
            const int px = p0 + wn0 + nf * 8 + cq * 2;
            if (px < HW) {
                float2 v0 = make_float2(acc[mf][nf][0] + b0, acc[mf][nf][1] + b0);
                float2 v1 = make_float2(acc[mf][nf][2] + b1, acc[mf][nf][3] + b1);
                *reinterpret_cast<float2*>(o0 + px) = v0;
                *reinterpret_cast<float2*>(o0 + (size_t)8 * HW + px) = v1;
            }
        }
    }
}

extern "C" void kernel_launch(void* const* d_in, const int* in_sizes, int n_in,
                              void* d_out, int out_size)
{
    const float* x    = (const float*)d_in[0];
    const float* W    = (const float*)d_in[1];
    const float* bias = (const float*)d_in[2];
    float* out        = (float*)d_out;

    static bool attr_done = false;
    if (!attr_done) {
        cudaFuncSetAttribute(conv_mma, cudaFuncAttributeMaxDynamicSharedMemorySize,
                             SMEM_BYTES);
        attr_done = true;
    }

    wf_kernel<<<72 * 2 * 2 * 32 * 16 / 256, 256>>>(W);
    xh_kernel<<<32 * 64 * PHW / 256, 256>>>(x);

    dim3 grid(25, 32, 2);
    conv_mma<<<grid, 128, SMEM_BYTES>>>(bias, out);
}

// round 11
// speedup vs baseline: 2.7818x; 1.1485x over previous
#include <cuda_runtime.h>
#include <cuda_fp16.h>
#include <cstdint>

// Conv2d 3x3 s1 p1 via mma.sync m16n8k16 FP16 (f32 accum) implicit GEMM.
// K order: chunk(64ch)-major, then tap, then k16. Per chunk, all 9 taps read one
// union window per channel-pair (up to 4 output rows + 2 pad rows = 352 words),
// staged ONCE (32 cpairs x 352 words, stride 360). 2 syncs total.
// A (weights): prepass packs per-thread fragments in consumption order; LDG.128
// pairwise register double-buffered. B: prepass packs fp16 channel-pairs into
// zero-padded [cpair][58x58] images.

#define HW    3136
#define PHW   3364            // 58*58
#define CIN   128
#define COUT  256
#define KTOT  1152
#define LDW   360             // window row stride (words); 360 mod 32 = 8
#define WROW  352             // staged words per row (88 cp16)
#define CHUNKW (32*LDW)       // 11520 words per chunk window
#define SMEM_BYTES ((2*CHUNKW + 64)*4)   // 92416 B

__device__ __align__(16) uint32_t g_wf[72 * 2 * 2 * 32 * 16];     // frags, consumption order
__device__ __align__(16) uint32_t g_xh[32 * 64 * PHW + 1024];     // packed fp16 x

// word w: reg=w&3, mf=(w>>2)&3, lane=(w>>4)&31, wmg=(w>>9)&1, oct=(w>>10)&1, kt16=w>>11
// kt16 = chunk*36 + tap*4 + h ; channels c = chunk*64 + h*16 + klocal ; rs = tap
__global__ void wf_kernel(const float* __restrict__ W) {
    const int w = blockIdx.x * 256 + threadIdx.x;
    const int reg = w & 3, mf = (w >> 2) & 3, lane = (w >> 4) & 31;
    const int wmg = (w >> 9) & 1, oct = (w >> 10) & 1, kt = w >> 11;
    const int chunk = kt / 36, rem = kt - chunk * 36;
    const int tap = rem >> 2, h = rem & 3;
    const int r = lane >> 2, cq = lane & 3;
    const int oc = oct * 128 + wmg * 64 + mf * 16 + r + (reg & 1) * 8;
    const int klocal = 2 * cq + ((reg & 2) ? 8 : 0);
    const int c = chunk * 64 + h * 16 + klocal;
    const __half2 hv = __floats2half2_rn(W[oc * KTOT + c * 9 + tap],
                                         W[oc * KTOT + (c + 1) * 9 + tap]);
    g_wf[w] = *reinterpret_cast<const uint32_t*>(&hv);
}

__global__ void xh_kernel(const float* __restrict__ x) {
    const int idx = blockIdx.x * 256 + threadIdx.x;
    const int cell = idx % PHW;
    const int cp = (idx / PHW) & 63;
    const int ni = idx / (PHW * 64);
    const int ph = cell / 58, pw = cell - ph * 58;
    float lo = 0.0f, hi = 0.0f;
    if (ph >= 1 && ph <= 56 && pw >= 1 && pw <= 56) {
        const size_t base = ((size_t)ni * CIN + 2 * cp) * HW + (ph - 1) * 56 + (pw - 1);
        lo = x[base];
        hi = x[base + HW];
    }
    const __half2 h = __floats2half2_rn(lo, hi);
    g_xh[idx] = *reinterpret_cast<const uint32_t*>(&h);
}

__device__ __forceinline__ void cp16(uint32_t d, const void* s) {
    asm volatile("cp.async.cg.shared.global [%0], [%1], 16;" :: "r"(d), "l"(s));
}
#define CP_COMMIT asm volatile("cp.async.commit_group;" ::: "memory")
#define CP_WAIT(n) asm volatile("cp.async.wait_group %0;" :: "n"(n) : "memory")

#define MMA16(acc, a, b0, b1) \
    asm volatile("mma.sync.aligned.m16n8k16.row.col.f32.f16.f16.f32 " \
        "{%0,%1,%2,%3}, {%4,%5,%6,%7}, {%8,%9}, {%0,%1,%2,%3};" \
        : "+f"((acc)[0]), "+f"((acc)[1]), "+f"((acc)[2]), "+f"((acc)[3]) \
        : "r"((a)[0]), "r"((a)[1]), "r"((a)[2]), "r"((a)[3]), "r"(b0), "r"(b1))

__global__ void __launch_bounds__(128, 2)
conv_mma(const float* __restrict__ bias, float* __restrict__ out)
{
    extern __shared__ uint32_t smW[];
    const uint32_t smb = (uint32_t)__cvta_generic_to_shared(smW);
    const int tid  = threadIdx.x;
    const int lane = tid & 31;
    const int wid  = tid >> 5;
    const int r    = lane >> 2, cq = lane & 3;
    const int p0   = blockIdx.x * 128;
    const int ni   = blockIdx.y;
    const int oct  = blockIdx.z;
    const int wmg  = wid & 1;
    const int wn0  = (wid >> 1) * 64;

    const int oh0 = p0 / 56;
    const int abase = (oh0 * 58) & ~3;        // aligned window start in padded img
    const int am0   = oh0 * 58 - abase;       // 0..3

    // per-thread B pixel offsets relative to window start (max 232 + am0)
    int pxr[8];
#pragma unroll
    for (int nf = 0; nf < 8; nf++) {
        int px = p0 + wn0 + nf * 8 + r;
        if (px >= HW) px = HW - 1;
        const int oh = px / 56, ow = px - oh * 56;
        pxr[nf] = oh * 58 + ow - oh0 * 58 + am0;
    }

    const uint32_t* xim = g_xh + (size_t)ni * (64 * PHW);

    float acc[4][8][4];
#pragma unroll
    for (int mf = 0; mf < 4; mf++)
#pragma unroll
        for (int nf = 0; nf < 8; nf++)
#pragma unroll
            for (int e = 0; e < 4; e++) acc[mf][nf][e] = 0.0f;

    // ---- stage one chunk window: 32 cpairs x 88 cp16 (352 words staged/row) ----
    auto issueChunk = [&](int chunk) {
        const int cp0 = chunk * 32;
        const uint32_t dst = smb + (chunk * CHUNKW) * 4;
#pragma unroll
        for (int q = 0; q < 22; q++) {          // 2816 items / 128 threads = 22
            const int it = tid + q * 128;
            const int row = it / 88;
            const int col = it - row * 88;
            cp16(dst + (row * LDW + col * 4) * 4,
                 xim + (size_t)(cp0 + row) * PHW + abase + col * 4);
        }
    };

    const uint32_t* wf0 = g_wf + ((size_t)oct * 2 + wmg) * 512 + lane * 16;
    auto loadA2 = [&](int P, uint32_t a[32]) {    // pair P -> kt16 2P, 2P+1
        const uint4* p  = reinterpret_cast<const uint4*>(wf0 + (size_t)(2 * P) * 2048);
        const uint4* p2 = reinterpret_cast<const uint4*>(wf0 + (size_t)(2 * P + 1) * 2048);
#pragma unroll
        for (int q = 0; q < 4; q++) {
            const uint4 v = p[q];
            a[q * 4 + 0] = v.x; a[q * 4 + 1] = v.y; a[q * 4 + 2] = v.z; a[q * 4 + 3] = v.w;
        }
#pragma unroll
        for (int q = 0; q < 4; q++) {
            const uint4 v = p2[q];
            a[16 + q * 4 + 0] = v.x; a[16 + q * 4 + 1] = v.y;
            a[16 + q * 4 + 2] = v.z; a[16 + q * 4 + 3] = v.w;
        }
    };

    issueChunk(0); CP_COMMIT;
    issueChunk(1); CP_COMMIT;

    uint32_t Ab[2][32];
    loadA2(0, Ab[0]);

#pragma unroll
    for (int chunk = 0; chunk < 2; chunk++) {
        if (chunk == 0) { CP_WAIT(1); } else { CP_WAIT(0); }
        __syncthreads();
        const uint32_t* win = smW + chunk * CHUNKW;

#pragma unroll 1
        for (int tap = 0; tap < 9; tap++) {
            const int rr = tap / 3, sc = tap - rr * 3;
            const int toff = rr * 58 + sc;
#pragma unroll
            for (int sp = 0; sp < 2; sp++) {           // k16-pair within tap
                const int gpair = chunk * 18 + tap * 2 + sp;
                if (gpair + 1 < 36) loadA2(gpair + 1, Ab[sp ^ 1]);
#pragma unroll
                for (int h2 = 0; h2 < 2; h2++) {       // k16 within pair
                    const int hrow = (sp * 2 + h2) * 8;
                    uint32_t b[8][2];
#pragma unroll
                    for (int nf = 0; nf < 8; nf++) {
                        b[nf][0] = win[(hrow + cq) * LDW + toff + pxr[nf]];
                        b[nf][1] = win[(hrow + cq + 4) * LDW + toff + pxr[nf]];
                    }
                    const uint32_t* af = Ab[sp] + h2 * 16;
#pragma unroll
                    for (int mf = 0; mf < 4; mf++)
#pragma unroll
                        for (int nf = 0; nf < 8; nf++)
                            MMA16(acc[mf][nf], af + mf * 4, b[nf][0], b[nf][1]);
                }
            }
        }
    }

    // ---- epilogue ----
    const size_t obase = (size_t)ni * COUT * HW;
#pragma unroll
    for (int mf = 0; mf < 4; mf++) {
        const int mg = oct * 128 + wmg * 64 + mf * 16 + r;
        const float b0 = __ldg(bias + mg);
        const float b1 = __ldg(bias + mg + 8);
        float* o0 = out + obase + (size_t)mg * HW;
#pragma unroll
        for (int nf = 0; nf < 8; nf++) {
            const int px = p0 + wn0 + nf * 8 + cq * 2;
            if (px < HW) {
                float2 v0 = make_float2(acc[mf][nf][0] + b0, acc[mf][nf][1] + b0);
                float2 v1 = make_float2(acc[mf][nf][2] + b1, acc[mf][nf][3] + b1);
                *reinterpret_cast<float2*>(o0 + px) = v0;
                *reinterpret_cast<float2*>(o0 + (size_t)8 * HW + px) = v1;
            }
        }
    }
}

extern "C" void kernel_launch(void* const* d_in, const int* in_sizes, int n_in,
                              void* d_out, int out_size)
{
    const float* x    = (const float*)d_in[0];
    const float* W    = (const float*)d_in[1];
    const float* bias = (const float*)d_in[2];
    float* out        = (float*)d_out;

    static bool attr_done = false;
    if (!attr_done) {
        cudaFuncSetAttribute(conv_mma, cudaFuncAttributeMaxDynamicSharedMemorySize,
                             SMEM_BYTES);
        attr_done = true;
    }

    wf_kernel<<<72 * 2 * 2 * 32 * 16 / 256, 256>>>(W);
    xh_kernel<<<32 * 64 * PHW / 256, 256>>>(x);

    dim3 grid(25, 32, 2);
    conv_mma<<<grid, 128, SMEM_BYTES>>>(bias, out);
}